// round 8
// baseline (speedup 1.0000x reference)
#include <cuda_runtime.h>
#include <math.h>

// ---------------------------------------------------------------------------
// FCOS3D target assignment — round 8: R7 structure + instruction-count cuts.
// (a) magic-multiply division replaces all runtime integer divides;
// (b) warp point-bbox derived from lane 0 / lane 31 coords via 6 shuffles
//     (level-boundary warps use an all-pass bbox — correct, just unpruned).
// Warp-autonomous: no __syncthreads, per-warp smem candidate segments,
// GT0 payload prefetched concurrently with the GT table load.
// ---------------------------------------------------------------------------

#define NLVL 5
#define NPTS 30929
#define INF_ 1.0e8f

__device__ __constant__ int   c_off[NLVL + 1] = {0, 23200, 29000, 30450, 30825, 30929};
__device__ __constant__ int   c_w[NLVL]       = {200, 100, 50, 25, 13};
// ceil(2^32 / w): exact floor(p/w) = umulhi(p, magic) for p < 2^30
__device__ __constant__ unsigned c_wmagic[NLVL] = {21474837u, 42949673u, 85899346u, 171798692u, 330382100u};
__device__ __constant__ float c_s[NLVL]       = {8.f, 16.f, 32.f, 64.f, 128.f};
__device__ __constant__ float c_xmax[NLVL]    = {1596.f, 1592.f, 1584.f, 1568.f, 1600.f}; // (w-1)*s + s/2
__device__ __constant__ float c_inv_s[NLVL]   = {0.125f, 0.0625f, 0.03125f, 0.015625f, 0.0078125f};
__device__ __constant__ float c_cent_k[NLVL]  = {
    -2.5f / (1.414f * 8.f   * 1.5f),
    -2.5f / (1.414f * 16.f  * 1.5f),
    -2.5f / (1.414f * 32.f  * 1.5f),
    -2.5f / (1.414f * 64.f  * 1.5f),
    -2.5f / (1.414f * 128.f * 1.5f)};
__device__ __constant__ float c_r0[NLVL]      = {-1.f, 48.f, 96.f, 192.f, 384.f};
__device__ __constant__ float c_r1[NLVL]      = {48.f, 96.f, 192.f, 384.f, 1.0e8f};

#define NWARP 4   // 128-thread blocks

__global__ void __launch_bounds__(128)
fcos3d_target_kernel(
    const float* __restrict__ gt_bboxes,    // (B, M, 4)
    const float* __restrict__ g3d,          // (B, M, 9)
    const int*   __restrict__ gl3d,         // (B, M)
    const float* __restrict__ centers2d,    // (B, M, 2)
    const float* __restrict__ depths,       // (B, M)
    const int*   __restrict__ attrs,        // (B, M)
    float*       __restrict__ out,
    int M, int B)
{
    const int b    = blockIdx.y;
    const int tid  = threadIdx.x;
    const int lane = tid & 31;
    const int wid  = tid >> 5;

    __shared__ float4 s_cbb[NWARP][64];
    __shared__ float2 s_cc[NWARP][64];
    __shared__ int    s_cidx[NWARP][64];

    // ---- point coords (clamped for warp convergence) ----
    const int n_raw = blockIdx.x * blockDim.x + tid;
    const bool valid = (n_raw < NPTS);
    const int n = valid ? n_raw : (NPTS - 1);

    int lvl = 0;
#pragma unroll
    for (int i = 1; i < NLVL; i++)
        if (n >= c_off[i]) lvl = i;

    const int   p   = n - c_off[lvl];
    const float s   = c_s[lvl];
    const int   row = (int)__umulhi((unsigned)p, c_wmagic[lvl]);
    const int   col = p - row * c_w[lvl];
    const float x   = fmaf((float)col, s, 0.5f * s);
    const float y   = fmaf((float)row, s, 0.5f * s);
    const float r0  = c_r0[lvl];
    const float r1  = c_r1[lvl];
    const float rad = s * 1.5f;

    // ---- issue all independent global loads up front ----
    const float2* cptr = reinterpret_cast<const float2*>(centers2d) + (size_t)b * M;
    const float4* bptr = reinterpret_cast<const float4*>(gt_bboxes) + (size_t)b * M;

    float2 myc[2];
    float4 mybb[2];
#pragma unroll
    for (int r = 0; r < 2; r++) {
        const int m = r * 32 + lane;
        if (m < M) { myc[r] = cptr[m]; mybb[r] = bptr[m]; }
        else       { myc[r] = make_float2(-2e30f, -2e30f); }
    }

    // GT0 payload prefetch (broadcast; covers the background majority).
    const int gi0 = b * M;
    const float* g0p = g3d + (size_t)gi0 * 9;
    float  p_g0 = g0p[0], p_g2 = g0p[2], p_g3 = g0p[3], p_g4 = g0p[4];
    float  p_g5 = g0p[5], p_g6 = g0p[6], p_g7 = g0p[7], p_g8 = g0p[8];
    float  p_d  = depths[gi0];
    float  p_l  = (float)gl3d[gi0];
    float  p_a  = (float)attrs[gi0];
    float2 c0   = cptr[0];

    // ---- warp point-bbox from lane 0 / lane 31 (6 shuffles) ----
    const float x0  = __shfl_sync(0xffffffffu, x, 0);
    const float x31 = __shfl_sync(0xffffffffu, x, 31);
    const float y0  = __shfl_sync(0xffffffffu, y, 0);
    const float y31 = __shfl_sync(0xffffffffu, y, 31);
    const int   l0  = __shfl_sync(0xffffffffu, lvl, 0);
    const int   l31 = __shfl_sync(0xffffffffu, lvl, 31);

    float bxmin, bxmax, bymin, bymax;
    if (l0 == l31) {
        const float rmx = c_s[l0] * 1.5f;
        const bool multirow = (y31 != y0);
        bymin = y0 - rmx;
        bymax = y31 + rmx;
        bxmin = (multirow ? 0.5f * c_s[l0] : x0) - rmx;
        bxmax = (multirow ? c_xmax[l0] : x31) + rmx;
    } else {  // level boundary inside warp (rare): all-pass bbox
        bxmin = -3e38f; bxmax = 3e38f; bymin = -3e38f; bymax = 3e38f;
    }

    // ---- ballot filter + ordered compaction into this warp's segment ----
    int cnt = 0;
#pragma unroll
    for (int r = 0; r < 2; r++) {
        const int m = r * 32 + lane;
        const bool ok = (m < M) &
                        (myc[r].x >= bxmin) & (myc[r].x <= bxmax) &
                        (myc[r].y >= bymin) & (myc[r].y <= bymax);
        const unsigned mask = __ballot_sync(0xffffffffu, ok);
        if (ok) {
            const int pos = cnt + __popc(mask & ((1u << lane) - 1u));
            s_cbb[wid][pos]  = mybb[r];
            s_cc[wid][pos]   = myc[r];
            s_cidx[wid][pos] = m;
        }
        cnt += __popc(mask);
    }
    __syncwarp();

    // ---- argmin over candidates (squared distance; first-min tie-break) ----
    float best = INF_;
    int   bk   = -1;
    for (int k = 0; k < cnt; k++) {
        const float4 bb = s_cbb[wid][k];
        const float2 c  = s_cc[wid][k];
        const float dx = x - c.x;
        const float dy = y - c.y;
        const float mrd = fmaxf(fmaxf(x - bb.x, y - bb.y),
                                fmaxf(bb.z - x, bb.w - y));
        const bool ok = (mrd >= r0) & (mrd <= r1) &
                        (fmaxf(fabsf(dx), fabsf(dy)) < rad);
        const float d2 = ok ? fmaf(dx, dx, dy * dy) : INF_;
        if (d2 < best) { best = d2; bk = k; }
    }

    if (!valid) return;

    // bk >= 0 <=> foreground. Background -> GT index 0 (reference semantics).
    const bool bg = (bk < 0);
    float2 c = c0;
    if (!bg) {
        c = s_cc[wid][bk];
        const int bi = s_cidx[wid][bk];
        const int gi = b * M + bi;
        const float* g = g3d + (size_t)gi * 9;
        p_g0 = g[0]; p_g2 = g[2]; p_g3 = g[3]; p_g4 = g[4];
        p_g5 = g[5]; p_g6 = g[6]; p_g7 = g[7]; p_g8 = g[8];
        p_d  = depths[gi];
        p_l  = (float)gl3d[gi];
        p_a  = (float)attrs[gi];
    }

    const float dx = x - c.x;
    const float dy = y - c.y;
    const float yaw  = -atan2f(p_g0, p_g2) + p_g6;
    const float cent = expf(c_cent_k[lvl] * sqrtf(fmaf(dx, dx, dy * dy)));

    const int BN   = B * NPTS;
    const int npl  = c_off[lvl + 1] - c_off[lvl];
    const int base = c_off[lvl] * B + b * npl + p;
    const float inv_s = c_inv_s[lvl];

    out[base]           = bg ? 10.f : p_l;   // labels_3d
    out[10 * BN + base] = cent;              // centerness
    out[11 * BN + base] = bg ? 9.f : p_a;    // attr

    float* bo = out + BN + (size_t)base * 9; // bbox_targets_3d
    bo[0] = dx * inv_s;
    bo[1] = dy * inv_s;
    bo[2] = p_d;
    bo[3] = p_g3;
    bo[4] = p_g4;
    bo[5] = p_g5;
    bo[6] = yaw;
    bo[7] = p_g7;
    bo[8] = p_g8;
}

extern "C" void kernel_launch(void* const* d_in, const int* in_sizes, int n_in,
                              void* d_out, int out_size)
{
    const float* gt_bboxes = (const float*)d_in[0];
    const float* g3d       = (const float*)d_in[2];
    const int*   gl3d      = (const int*)  d_in[3];
    const float* centers2d = (const float*)d_in[4];
    const float* depths    = (const float*)d_in[5];
    const int*   attrs     = (const int*)  d_in[6];
    float* out = (float*)d_out;

    const int B = out_size / (12 * NPTS);
    const int M = in_sizes[1] / B;

    const int threads = 128;
    dim3 grid((NPTS + threads - 1) / threads, B);
    fcos3d_target_kernel<<<grid, threads>>>(
        gt_bboxes, g3d, gl3d, centers2d, depths, attrs, out, M, B);
}